// round 1
// baseline (speedup 1.0000x reference)
#include <cuda_runtime.h>
#include <math.h>

#define BB 4
#define NN 4096      // 64*64 spatial
#define CC 128       // channels
#define BM 128
#define BN 128
#define BK 32
#define NCT (NN / BN)   // 32 column tiles

// Scratch (device globals: allocation-free per harness rules)
__device__ float g_S[(size_t)BB * NN * NN];   // 256 MB similarity matrix
__device__ float g_X[BB * NN * CC];           // normalized x  [b][n][c]
__device__ float g_Y[BB * NN * CC];           // normalized y
__device__ float g_mean[BB * CC];
__device__ float g_rmax[BB * NN * NCT];       // per (row, colTile) partial max of s
__device__ float g_cx[BB];

// ---------------------------------------------------------------- init
__global__ void k_init() {
    int i = blockIdx.x * blockDim.x + threadIdx.x;
    if (i < BB) g_cx[i] = 0.f;
    if (i < BB * CC) g_mean[i] = 0.f;
}

// ---------------------------------------------------------------- mean of y over spatial
__global__ void k_mean(const float* __restrict__ fy) {
    // grid (BB, 32), 128 threads; block sums 128 rows for all c
    int b = blockIdx.x, chunk = blockIdx.y;
    int c = threadIdx.x;
    float s = 0.f;
    int n0 = chunk * 128;
    const float* base = fy + ((size_t)b * NN + n0) * CC + c;
#pragma unroll 4
    for (int n = 0; n < 128; n++)
        s += base[(size_t)n * CC];
    atomicAdd(&g_mean[b * CC + c], s * (1.0f / NN));
}

// ---------------------------------------------------------------- center + normalize
__global__ void k_norm(const float* __restrict__ fx, const float* __restrict__ fy) {
    // one warp per row (B*N rows), 8 warps/block
    int gw = blockIdx.x * 8 + (threadIdx.x >> 5);
    int lane = threadIdx.x & 31;
    int b = gw / NN;
    const float4* xr = (const float4*)(fx + (size_t)gw * CC);
    const float4* yr = (const float4*)(fy + (size_t)gw * CC);
    const float4* mr = (const float4*)(g_mean + b * CC);
    float4 m = mr[lane];
    float4 x = xr[lane];
    float4 y = yr[lane];
    x.x -= m.x; x.y -= m.y; x.z -= m.z; x.w -= m.w;
    y.x -= m.x; y.y -= m.y; y.z -= m.z; y.w -= m.w;
    float sx = x.x * x.x + x.y * x.y + x.z * x.z + x.w * x.w;
    float sy = y.x * y.x + y.y * y.y + y.z * y.z + y.w * y.w;
#pragma unroll
    for (int o = 16; o > 0; o >>= 1) {
        sx += __shfl_xor_sync(0xFFFFFFFFu, sx, o);
        sy += __shfl_xor_sync(0xFFFFFFFFu, sy, o);
    }
    float ix = 1.0f / (sqrtf(sx) + 1e-10f);
    float iy = 1.0f / (sqrtf(sy) + 1e-10f);
    float4* xo = (float4*)(g_X + (size_t)gw * CC);
    float4* yo = (float4*)(g_Y + (size_t)gw * CC);
    xo[lane] = make_float4(x.x * ix, x.y * ix, x.z * ix, x.w * ix);
    yo[lane] = make_float4(y.x * iy, y.y * iy, y.z * iy, y.w * iy);
}

// ---------------------------------------------------------------- batched GEMM S = Xn * Yn^T
// + per-(row, colTile) partial max in the epilogue
__global__ void __launch_bounds__(256) k_gemm() {
    __shared__ float As[BK][BM + 4];
    __shared__ float Bs[BK][BN + 4];

    int b = blockIdx.z;
    int n0 = blockIdx.y * BM;
    int m0 = blockIdx.x * BN;
    int tid = threadIdx.x;
    int tx = tid & 15;        // 16 in m
    int ty = tid >> 4;        // 16 in n

    const float* Xb = g_X + (size_t)b * NN * CC;
    const float* Yb = g_Y + (size_t)b * NN * CC;

    float acc[8][8];
#pragma unroll
    for (int i = 0; i < 8; i++)
#pragma unroll
        for (int j = 0; j < 8; j++) acc[i][j] = 0.f;

    for (int kt = 0; kt < CC; kt += BK) {
        // load A tile (transposed to [k][n]) and B tile ([k][m])
#pragma unroll
        for (int i = 0; i < 4; i++) {
            int f = i * 256 + tid;          // 0..1023 float4 slots
            int row = f >> 3;               // 0..127
            int kc = (f & 7) << 2;          // 0,4,...,28
            float4 va = *(const float4*)&Xb[(size_t)(n0 + row) * CC + kt + kc];
            As[kc + 0][row] = va.x; As[kc + 1][row] = va.y;
            As[kc + 2][row] = va.z; As[kc + 3][row] = va.w;
            float4 vb = *(const float4*)&Yb[(size_t)(m0 + row) * CC + kt + kc];
            Bs[kc + 0][row] = vb.x; Bs[kc + 1][row] = vb.y;
            Bs[kc + 2][row] = vb.z; Bs[kc + 3][row] = vb.w;
        }
        __syncthreads();

#pragma unroll
        for (int k = 0; k < BK; k++) {
            float4 a0 = *(const float4*)&As[k][ty * 8];
            float4 a1 = *(const float4*)&As[k][ty * 8 + 4];
            float4 b0 = *(const float4*)&Bs[k][tx * 8];
            float4 b1 = *(const float4*)&Bs[k][tx * 8 + 4];
            float ar[8] = {a0.x, a0.y, a0.z, a0.w, a1.x, a1.y, a1.z, a1.w};
            float br[8] = {b0.x, b0.y, b0.z, b0.w, b1.x, b1.y, b1.z, b1.w};
#pragma unroll
            for (int i = 0; i < 8; i++)
#pragma unroll
                for (int j = 0; j < 8; j++) acc[i][j] += ar[i] * br[j];
        }
        __syncthreads();
    }

    // write S tile + per-thread row maxes
    float* red = &As[0][0];   // reuse: 128 rows x 16 tx = 8 KB
#pragma unroll
    for (int r = 0; r < 8; r++) {
        size_t base = ((size_t)b * NN + n0 + ty * 8 + r) * NN + m0 + tx * 8;
        *(float4*)&g_S[base]     = make_float4(acc[r][0], acc[r][1], acc[r][2], acc[r][3]);
        *(float4*)&g_S[base + 4] = make_float4(acc[r][4], acc[r][5], acc[r][6], acc[r][7]);
        float mx = acc[r][0];
#pragma unroll
        for (int j = 1; j < 8; j++) mx = fmaxf(mx, acc[r][j]);
        red[(ty * 8 + r) * 16 + tx] = mx;
    }
    __syncthreads();
    if (tid < 128) {
        float mx = red[tid * 16];
#pragma unroll
        for (int j = 1; j < 16; j++) mx = fmaxf(mx, red[tid * 16 + j]);
        g_rmax[((size_t)b * NN + n0 + tid) * NCT + blockIdx.x] = mx;
    }
}

// ---------------------------------------------------------------- per-row exp-sum
__global__ void __launch_bounds__(256) k_row() {
    int row = blockIdx.x;          // over B*N
    int b = row / NN;
    int tid = threadIdx.x;
    int lane = tid & 31, wid = tid >> 5;

    __shared__ float sh_smax;
    __shared__ float warpsum[8];

    float m = -1e30f;
    if (tid < NCT) m = g_rmax[(size_t)row * NCT + tid];
#pragma unroll
    for (int o = 16; o > 0; o >>= 1) m = fmaxf(m, __shfl_xor_sync(0xFFFFFFFFu, m, o));
    if (tid == 0) sh_smax = m;
    __syncthreads();
    float smax = sh_smax;
    float c = (1.0f - smax) + 0.001f;   // dmin + eps
    float beta = 10.0f / c;             // 1/(c*h), h = 0.1

    const float4* s4 = (const float4*)&g_S[(size_t)row * NN];
    float sum = 0.f;
    for (int i = tid; i < NN / 4; i += 256) {
        float4 v = s4[i];
        sum += __expf(beta * (v.x - smax));
        sum += __expf(beta * (v.y - smax));
        sum += __expf(beta * (v.z - smax));
        sum += __expf(beta * (v.w - smax));
    }
#pragma unroll
    for (int o = 16; o > 0; o >>= 1) sum += __shfl_xor_sync(0xFFFFFFFFu, sum, o);
    if (lane == 0) warpsum[wid] = sum;
    __syncthreads();
    if (tid < 8) {
        float s = warpsum[tid];
#pragma unroll
        for (int o = 4; o > 0; o >>= 1) s += __shfl_xor_sync(0xFFu, s, o);
        if (tid == 0) atomicAdd(&g_cx[b], 1.0f / s);   // A_max for this row
    }
}

// ---------------------------------------------------------------- finalize
__global__ void k_fin(float* __restrict__ out) {
    int b = threadIdx.x;
    if (b < BB) out[b] = -logf(g_cx[b] * (1.0f / NN));
}

// ---------------------------------------------------------------- launcher
extern "C" void kernel_launch(void* const* d_in, const int* in_sizes, int n_in,
                              void* d_out, int out_size) {
    const float* fx = (const float*)d_in[0];
    const float* fy = (const float*)d_in[1];
    float* out = (float*)d_out;

    k_init<<<1, 512>>>();
    k_mean<<<dim3(BB, 32), 128>>>(fy);
    k_norm<<<(BB * NN) / 8, 256>>>(fx, fy);
    k_gemm<<<dim3(NCT, NN / BM, BB), 256>>>();
    k_row<<<BB * NN, 256>>>();
    k_fin<<<1, 32>>>(out);
}

// round 4
// speedup vs baseline: 3.7794x; 3.7794x over previous
#include <cuda_runtime.h>
#include <cuda_bf16.h>
#include <math.h>
#include <cstdint>

#define BB 4
#define NN 4096
#define CC 128
#define NT 32           // 4096/128 m-tiles

// ------------------------------------------------------------------ scratch
__device__ __nv_bfloat16 g_Xh[(size_t)BB * NN * CC];
__device__ __nv_bfloat16 g_Yh[(size_t)BB * NN * CC];
__device__ float g_mean[BB * CC];
__device__ float g_smax[BB * NN];
__device__ float g_cx[BB];

// ------------------------------------------------------------------ helpers
__device__ __forceinline__ uint32_t smem_u32(const void* p) {
    uint32_t a;
    asm("{ .reg .u64 t; cvta.to.shared.u64 t, %1; cvt.u32.u64 %0, t; }" : "=r"(a) : "l"(p));
    return a;
}
__device__ __forceinline__ void cp16(uint32_t dst, const void* src) {
    asm volatile("cp.async.cg.shared.global [%0], [%1], 16;" :: "r"(dst), "l"(src));
}
#define CP_COMMIT() asm volatile("cp.async.commit_group;" ::: "memory")
#define CP_WAIT0()  asm volatile("cp.async.wait_group 0;" ::: "memory")

#define LDSM4(r0, r1, r2, r3, addr)                                              \
    asm volatile("ldmatrix.sync.aligned.m8n8.x4.shared.b16 {%0,%1,%2,%3}, [%4];" \
        : "=r"(r0), "=r"(r1), "=r"(r2), "=r"(r3) : "r"(addr))

__device__ __forceinline__ void mma_bf16(float* d, const uint32_t* a, uint32_t b0, uint32_t b1) {
    asm volatile(
        "mma.sync.aligned.m16n8k16.row.col.f32.bf16.bf16.f32 "
        "{%0,%1,%2,%3}, {%4,%5,%6,%7}, {%8,%9}, {%0,%1,%2,%3};"
        : "+f"(d[0]), "+f"(d[1]), "+f"(d[2]), "+f"(d[3])
        : "r"(a[0]), "r"(a[1]), "r"(a[2]), "r"(a[3]), "r"(b0), "r"(b1));
}

// smem tile layout: 128 rows x 256B, xor-swizzled 16B units
__device__ __forceinline__ uint32_t toff(int r, int u) {
    return (uint32_t)(r * 256 + ((u ^ (r & 7)) << 4));
}

// ------------------------------------------------------------------ small kernels
__global__ void k_init() {
    int i = blockIdx.x * blockDim.x + threadIdx.x;
    if (i < BB) g_cx[i] = 0.f;
    if (i < BB * CC) g_mean[i] = 0.f;
}

__global__ void k_mean(const float* __restrict__ fy) {
    int b = blockIdx.x, chunk = blockIdx.y;
    int c = threadIdx.x;
    float s = 0.f;
    const float* base = fy + ((size_t)b * NN + chunk * 128) * CC + c;
#pragma unroll 4
    for (int n = 0; n < 128; n++) s += base[(size_t)n * CC];
    atomicAdd(&g_mean[b * CC + c], s * (1.0f / NN));
}

__global__ void k_norm(const float* __restrict__ fx, const float* __restrict__ fy) {
    int gw = blockIdx.x * 8 + (threadIdx.x >> 5);
    int lane = threadIdx.x & 31;
    int b = gw / NN;
    float4 m = ((const float4*)(g_mean + b * CC))[lane];
    float4 x = ((const float4*)(fx + (size_t)gw * CC))[lane];
    float4 y = ((const float4*)(fy + (size_t)gw * CC))[lane];
    x.x -= m.x; x.y -= m.y; x.z -= m.z; x.w -= m.w;
    y.x -= m.x; y.y -= m.y; y.z -= m.z; y.w -= m.w;
    float sx = x.x * x.x + x.y * x.y + x.z * x.z + x.w * x.w;
    float sy = y.x * y.x + y.y * y.y + y.z * y.z + y.w * y.w;
#pragma unroll
    for (int o = 16; o > 0; o >>= 1) {
        sx += __shfl_xor_sync(0xFFFFFFFFu, sx, o);
        sy += __shfl_xor_sync(0xFFFFFFFFu, sy, o);
    }
    float ix = 1.0f / (sqrtf(sx) + 1e-10f);
    float iy = 1.0f / (sqrtf(sy) + 1e-10f);
    __nv_bfloat162 xp0 = __floats2bfloat162_rn(x.x * ix, x.y * ix);
    __nv_bfloat162 xp1 = __floats2bfloat162_rn(x.z * ix, x.w * ix);
    __nv_bfloat162 yp0 = __floats2bfloat162_rn(y.x * iy, y.y * iy);
    __nv_bfloat162 yp1 = __floats2bfloat162_rn(y.z * iy, y.w * iy);
    uint2 xv, yv;
    xv.x = *(uint32_t*)&xp0; xv.y = *(uint32_t*)&xp1;
    yv.x = *(uint32_t*)&yp0; yv.y = *(uint32_t*)&yp1;
    ((uint2*)(g_Xh + (size_t)gw * CC))[lane] = xv;
    ((uint2*)(g_Yh + (size_t)gw * CC))[lane] = yv;
}

// ------------------------------------------------------------------ fused GEMM passes
// smem: X tile 32KB | Y buf0 32KB | Y buf1 32KB | RED 128x2 f32 | BETA 128 | CV 128
#define XS_OFF 0
#define YS_OFF 32768
#define RED_OFF 98304
#define BETA_OFF 99328
#define CV_OFF 99840
#define SMEM_BYTES 100352

// PASS 0: row max of s over all m.  PASS 1: row sum of exp(beta*(s - smax)).
template <int PASS>
__global__ void __launch_bounds__(256) k_cx() {
    extern __shared__ char smem[];
    uint32_t sb = smem_u32(smem);
    float* RED  = (float*)(smem + RED_OFF);
    float* BETA = (float*)(smem + BETA_OFF);
    float* CV   = (float*)(smem + CV_OFF);

    int tid = threadIdx.x;
    int wid = tid >> 5, lane = tid & 31;
    int wy = wid >> 1;          // n-block 0..3 (rows of x)
    int wx = wid & 1;           // m-block 0..1 (cols / y rows)
    int b = blockIdx.y;
    int n0 = blockIdx.x * 128;

    const __nv_bfloat16* Xb = g_Xh + ((size_t)b * NN + n0) * CC;
    const __nv_bfloat16* Yb = g_Yh + (size_t)b * NN * CC;

    if (PASS == 1 && tid < 128) {
        float sm = g_smax[b * NN + n0 + tid];
        float be = 10.0f / ((1.0f - sm) + 0.001f);
        BETA[tid] = be;
        CV[tid] = be * sm;
    }

    // prologue: X tile + Y tile 0
#pragma unroll
    for (int i = 0; i < 8; i++) {
        int idx = i * 256 + tid;
        int r = idx >> 4, u = idx & 15;
        cp16(sb + XS_OFF + toff(r, u), Xb + r * CC + u * 8);
        cp16(sb + YS_OFF + toff(r, u), Yb + r * CC + u * 8);
    }
    CP_COMMIT();
    CP_WAIT0();
    __syncthreads();

    // ldmatrix base addresses (lane-dependent), kt part added per step
    int hi = lane >> 4;
    uint32_t aB[2], aS[2];
#pragma unroll
    for (int mi = 0; mi < 2; mi++) {
        int r = wy * 32 + mi * 16 + (lane & 15);
        aB[mi] = sb + XS_OFF + (uint32_t)(r * 256);
        aS[mi] = (uint32_t)(r & 7);
    }
    uint32_t bB[4], bS[4];
#pragma unroll
    for (int g = 0; g < 4; g++) {
        int r = wx * 64 + g * 16 + (lane & 15);
        bB[g] = (uint32_t)(r * 256);   // relative; Y buffer base added per iter
        bS[g] = (uint32_t)(r & 7);
    }

    // per-thread row state
    float racc[4];
    float lb[4], lc[4];
#pragma unroll
    for (int i = 0; i < 4; i++) racc[i] = (PASS == 0) ? -1e30f : 0.f;
    if (PASS == 1) {
#pragma unroll
        for (int mi = 0; mi < 2; mi++)
#pragma unroll
            for (int h = 0; h < 2; h++) {
                int lr = wy * 32 + mi * 16 + (lane >> 2) + h * 8;
                lb[mi * 2 + h] = BETA[lr];
                lc[mi * 2 + h] = CV[lr];
            }
    }

    for (int mt = 0; mt < NT; mt++) {
        int cur = mt & 1;
        if (mt + 1 < NT) {
            const __nv_bfloat16* Yt = Yb + (size_t)(mt + 1) * 128 * CC;
            uint32_t dstb = sb + YS_OFF + (cur ^ 1) * 32768;
#pragma unroll
            for (int i = 0; i < 8; i++) {
                int idx = i * 256 + tid;
                int r = idx >> 4, u = idx & 15;
                cp16(dstb + toff(r, u), Yt + r * CC + u * 8);
            }
            CP_COMMIT();
        }
        uint32_t ybase = sb + YS_OFF + cur * 32768;

        float acc[2][8][4];
#pragma unroll
        for (int mi = 0; mi < 2; mi++)
#pragma unroll
            for (int nj = 0; nj < 8; nj++)
#pragma unroll
                for (int k = 0; k < 4; k++) acc[mi][nj][k] = 0.f;

#pragma unroll
        for (int kt = 0; kt < 8; kt++) {
            uint32_t a[2][4];
#pragma unroll
            for (int mi = 0; mi < 2; mi++) {
                uint32_t addr = aB[mi] + ((uint32_t)((kt * 2 + hi) ^ aS[mi]) << 4);
                LDSM4(a[mi][0], a[mi][1], a[mi][2], a[mi][3], addr);
            }
            uint32_t bf[4][4];
#pragma unroll
            for (int g = 0; g < 4; g++) {
                uint32_t addr = ybase + bB[g] + ((uint32_t)((kt * 2 + hi) ^ bS[g]) << 4);
                LDSM4(bf[g][0], bf[g][1], bf[g][2], bf[g][3], addr);
            }
#pragma unroll
            for (int mi = 0; mi < 2; mi++)
#pragma unroll
                for (int g = 0; g < 4; g++) {
                    mma_bf16(acc[mi][2 * g],     a[mi], bf[g][0], bf[g][2]);
                    mma_bf16(acc[mi][2 * g + 1], a[mi], bf[g][1], bf[g][3]);
                }
        }

        // register epilogue
        if (PASS == 0) {
#pragma unroll
            for (int mi = 0; mi < 2; mi++)
#pragma unroll
                for (int nj = 0; nj < 8; nj++) {
                    racc[mi * 2]     = fmaxf(racc[mi * 2],     fmaxf(acc[mi][nj][0], acc[mi][nj][1]));
                    racc[mi * 2 + 1] = fmaxf(racc[mi * 2 + 1], fmaxf(acc[mi][nj][2], acc[mi][nj][3]));
                }
        } else {
#pragma unroll
            for (int mi = 0; mi < 2; mi++)
#pragma unroll
                for (int nj = 0; nj < 8; nj++) {
                    float b0 = lb[mi * 2], c0 = lc[mi * 2];
                    float b1 = lb[mi * 2 + 1], c1 = lc[mi * 2 + 1];
                    racc[mi * 2]     += __expf(fmaf(b0, acc[mi][nj][0], -c0))
                                      + __expf(fmaf(b0, acc[mi][nj][1], -c0));
                    racc[mi * 2 + 1] += __expf(fmaf(b1, acc[mi][nj][2], -c1))
                                      + __expf(fmaf(b1, acc[mi][nj][3], -c1));
                }
        }
        CP_WAIT0();
        __syncthreads();
    }

    // reduce across the 4 lanes of each quad (cols within n8)
#pragma unroll
    for (int i = 0; i < 4; i++) {
#pragma unroll
        for (int o = 1; o <= 2; o <<= 1) {
            float v = __shfl_xor_sync(0xFFFFFFFFu, racc[i], o);
            racc[i] = (PASS == 0) ? fmaxf(racc[i], v) : (racc[i] + v);
        }
    }
    if ((lane & 3) == 0) {
#pragma unroll
        for (int mi = 0; mi < 2; mi++)
#pragma unroll
            for (int h = 0; h < 2; h++) {
                int lr = wy * 32 + mi * 16 + (lane >> 2) + h * 8;
                RED[lr * 2 + wx] = racc[mi * 2 + h];
            }
    }
    __syncthreads();

    if (PASS == 0) {
        if (tid < 128)
            g_smax[b * NN + n0 + tid] = fmaxf(RED[tid * 2], RED[tid * 2 + 1]);
    } else {
        float amax = 0.f;
        if (tid < 128) amax = 1.0f / (RED[tid * 2] + RED[tid * 2 + 1]);
        __syncthreads();
#pragma unroll
        for (int o = 16; o > 0; o >>= 1) amax += __shfl_xor_sync(0xFFFFFFFFu, amax, o);
        if (lane == 0) RED[wid] = amax;
        __syncthreads();
        if (tid == 0) {
            float s = 0.f;
#pragma unroll
            for (int w = 0; w < 8; w++) s += RED[w];
            atomicAdd(&g_cx[b], s);
        }
    }
}

// ------------------------------------------------------------------ finalize
__global__ void k_fin(float* __restrict__ out) {
    int b = threadIdx.x;
    if (b < BB) out[b] = -logf(g_cx[b] * (1.0f / NN));
}

// ------------------------------------------------------------------ launcher
extern "C" void kernel_launch(void* const* d_in, const int* in_sizes, int n_in,
                              void* d_out, int out_size) {
    const float* fx = (const float*)d_in[0];
    const float* fy = (const float*)d_in[1];
    float* out = (float*)d_out;

    cudaFuncSetAttribute(k_cx<0>, cudaFuncAttributeMaxDynamicSharedMemorySize, SMEM_BYTES);
    cudaFuncSetAttribute(k_cx<1>, cudaFuncAttributeMaxDynamicSharedMemorySize, SMEM_BYTES);

    k_init<<<1, 512>>>();
    k_mean<<<dim3(BB, 32), 128>>>(fy);
    k_norm<<<(BB * NN) / 8, 256>>>(fx, fy);
    k_cx<0><<<dim3(NT, BB), 256, SMEM_BYTES>>>();
    k_cx<1><<<dim3(NT, BB), 256, SMEM_BYTES>>>();
    k_fin<<<1, 32>>>(out);
}

// round 8
// speedup vs baseline: 3.8382x; 1.0156x over previous
#include <cuda_runtime.h>
#include <cuda_bf16.h>
#include <math.h>
#include <cstdint>

#define BB 4
#define NN 4096
#define CC 128
#define NT 32           // 4096/128 m-tiles

// ------------------------------------------------------------------ scratch
__device__ __nv_bfloat16 g_Xh[(size_t)BB * NN * CC];
__device__ __nv_bfloat16 g_Yh[(size_t)BB * NN * CC];
__device__ float g_mean[BB * CC];
__device__ float g_cx[BB];

// ------------------------------------------------------------------ helpers
__device__ __forceinline__ uint32_t smem_u32(const void* p) {
    uint32_t a;
    asm("{ .reg .u64 t; cvta.to.shared.u64 t, %1; cvt.u32.u64 %0, t; }" : "=r"(a) : "l"(p));
    return a;
}
__device__ __forceinline__ void cp16(uint32_t dst, const void* src) {
    asm volatile("cp.async.cg.shared.global [%0], [%1], 16;" :: "r"(dst), "l"(src));
}
#define CP_COMMIT() asm volatile("cp.async.commit_group;" ::: "memory")
#define CP_WAIT0()  asm volatile("cp.async.wait_group 0;" ::: "memory")

#define LDSM4(r0, r1, r2, r3, addr)                                              \
    asm volatile("ldmatrix.sync.aligned.m8n8.x4.shared.b16 {%0,%1,%2,%3}, [%4];" \
        : "=r"(r0), "=r"(r1), "=r"(r2), "=r"(r3) : "r"(addr))

__device__ __forceinline__ void mma_bf16(float* d, const uint32_t* a, uint32_t b0, uint32_t b1) {
    asm volatile(
        "mma.sync.aligned.m16n8k16.row.col.f32.bf16.bf16.f32 "
        "{%0,%1,%2,%3}, {%4,%5,%6,%7}, {%8,%9}, {%0,%1,%2,%3};"
        : "+f"(d[0]), "+f"(d[1]), "+f"(d[2]), "+f"(d[3])
        : "r"(a[0]), "r"(a[1]), "r"(a[2]), "r"(a[3]), "r"(b0), "r"(b1));
}

// smem tile layout: 128 rows x 256B, xor-swizzled 16B units
__device__ __forceinline__ uint32_t toff(int r, int u) {
    return (uint32_t)(r * 256 + ((u ^ (r & 7)) << 4));
}

// ------------------------------------------------------------------ small kernels
__global__ void k_init() {
    int i = blockIdx.x * blockDim.x + threadIdx.x;
    if (i < BB) g_cx[i] = 0.f;
    if (i < BB * CC) g_mean[i] = 0.f;
}

__global__ void k_mean(const float* __restrict__ fy) {
    int b = blockIdx.x, chunk = blockIdx.y;
    int c = threadIdx.x;
    float s = 0.f;
    const float* base = fy + ((size_t)b * NN + chunk * 128) * CC + c;
#pragma unroll 4
    for (int n = 0; n < 128; n++) s += base[(size_t)n * CC];
    atomicAdd(&g_mean[b * CC + c], s * (1.0f / NN));
}

__global__ void k_norm(const float* __restrict__ fx, const float* __restrict__ fy) {
    int gw = blockIdx.x * 8 + (threadIdx.x >> 5);
    int lane = threadIdx.x & 31;
    int b = gw / NN;
    float4 m = ((const float4*)(g_mean + b * CC))[lane];
    float4 x = ((const float4*)(fx + (size_t)gw * CC))[lane];
    float4 y = ((const float4*)(fy + (size_t)gw * CC))[lane];
    x.x -= m.x; x.y -= m.y; x.z -= m.z; x.w -= m.w;
    y.x -= m.x; y.y -= m.y; y.z -= m.z; y.w -= m.w;
    float sx = x.x * x.x + x.y * x.y + x.z * x.z + x.w * x.w;
    float sy = y.x * y.x + y.y * y.y + y.z * y.z + y.w * y.w;
#pragma unroll
    for (int o = 16; o > 0; o >>= 1) {
        sx += __shfl_xor_sync(0xFFFFFFFFu, sx, o);
        sy += __shfl_xor_sync(0xFFFFFFFFu, sy, o);
    }
    float ix = 1.0f / (sqrtf(sx) + 1e-10f);
    float iy = 1.0f / (sqrtf(sy) + 1e-10f);
    __nv_bfloat162 xp0 = __floats2bfloat162_rn(x.x * ix, x.y * ix);
    __nv_bfloat162 xp1 = __floats2bfloat162_rn(x.z * ix, x.w * ix);
    __nv_bfloat162 yp0 = __floats2bfloat162_rn(y.x * iy, y.y * iy);
    __nv_bfloat162 yp1 = __floats2bfloat162_rn(y.z * iy, y.w * iy);
    uint2 xv, yv;
    xv.x = *(uint32_t*)&xp0; xv.y = *(uint32_t*)&xp1;
    yv.x = *(uint32_t*)&yp0; yv.y = *(uint32_t*)&yp1;
    ((uint2*)(g_Xh + (size_t)gw * CC))[lane] = xv;
    ((uint2*)(g_Yh + (size_t)gw * CC))[lane] = yv;
}

// ------------------------------------------------------------------ fused two-phase kernel
// smem: X 32KB | Y buf0 32KB | Y buf1 32KB | RED 128x4 f32 | BETA 128 | CV 128
#define XS_OFF 0
#define YS_OFF 32768
#define RED_OFF 98304
#define BETA_OFF 100352
#define CV_OFF 100864
#define SMEM_BYTES 101376

__device__ __forceinline__ void load_tile(uint32_t dstb, const __nv_bfloat16* src, int tid) {
#pragma unroll
    for (int i = 0; i < 4; i++) {
        int idx = i * 512 + tid;
        int r = idx >> 4, u = idx & 15;
        cp16(dstb + toff(r, u), src + r * CC + u * 8);
    }
}

__global__ void __launch_bounds__(512) k_fused() {
    extern __shared__ char smem[];
    uint32_t sb = smem_u32(smem);
    float* RED  = (float*)(smem + RED_OFF);    // [128][4]
    float* BETA = (float*)(smem + BETA_OFF);
    float* CV   = (float*)(smem + CV_OFF);

    int tid = threadIdx.x;
    int wid = tid >> 5, lane = tid & 31;
    int wy = wid >> 2;          // 0..3  row block (32 rows)
    int wx = wid & 3;           // 0..3  col block (32 cols)
    int b = blockIdx.y;
    int n0 = blockIdx.x * 128;

    const __nv_bfloat16* Xb = g_Xh + ((size_t)b * NN + n0) * CC;
    const __nv_bfloat16* Yb = g_Yh + (size_t)b * NN * CC;

    // prologue: X + Y tile 0
    load_tile(sb + XS_OFF, Xb, tid);
    load_tile(sb + YS_OFF, Yb, tid);
    CP_COMMIT();
    CP_WAIT0();
    __syncthreads();

    // ldmatrix addressing
    int hi = lane >> 4;
    uint32_t aB[2], aS[2];
#pragma unroll
    for (int mi = 0; mi < 2; mi++) {
        int r = wy * 32 + mi * 16 + (lane & 15);
        aB[mi] = sb + XS_OFF + (uint32_t)(r * 256);
        aS[mi] = (uint32_t)(r & 7);
    }
    uint32_t bB[2], bS[2];
#pragma unroll
    for (int g = 0; g < 2; g++) {
        int r = wx * 32 + g * 16 + (lane & 15);
        bB[g] = (uint32_t)(r * 256);
        bS[g] = (uint32_t)(r & 7);
    }

    // ---------------- PHASE 0: row max ----------------
    float rmax[4];
#pragma unroll
    for (int i = 0; i < 4; i++) rmax[i] = -1e30f;

    for (int mt = 0; mt < NT; mt++) {
        int cur = mt & 1;
        if (mt + 1 < NT) {
            load_tile(sb + YS_OFF + (cur ^ 1) * 32768, Yb + (size_t)(mt + 1) * 128 * CC, tid);
            CP_COMMIT();
        }
        uint32_t ybase = sb + YS_OFF + cur * 32768;

        float acc[2][4][4];
#pragma unroll
        for (int mi = 0; mi < 2; mi++)
#pragma unroll
            for (int nj = 0; nj < 4; nj++)
#pragma unroll
                for (int k = 0; k < 4; k++) acc[mi][nj][k] = 0.f;

#pragma unroll
        for (int kt = 0; kt < 8; kt++) {
            uint32_t a[2][4], bf[2][4];
#pragma unroll
            for (int mi = 0; mi < 2; mi++) {
                uint32_t addr = aB[mi] + ((uint32_t)((kt * 2 + hi) ^ aS[mi]) << 4);
                LDSM4(a[mi][0], a[mi][1], a[mi][2], a[mi][3], addr);
            }
#pragma unroll
            for (int g = 0; g < 2; g++) {
                uint32_t addr = ybase + bB[g] + ((uint32_t)((kt * 2 + hi) ^ bS[g]) << 4);
                LDSM4(bf[g][0], bf[g][1], bf[g][2], bf[g][3], addr);
            }
#pragma unroll
            for (int mi = 0; mi < 2; mi++)
#pragma unroll
                for (int g = 0; g < 2; g++) {
                    mma_bf16(acc[mi][2 * g],     a[mi], bf[g][0], bf[g][2]);
                    mma_bf16(acc[mi][2 * g + 1], a[mi], bf[g][1], bf[g][3]);
                }
        }
#pragma unroll
        for (int mi = 0; mi < 2; mi++)
#pragma unroll
            for (int nj = 0; nj < 4; nj++) {
                rmax[mi * 2]     = fmaxf(rmax[mi * 2],     fmaxf(acc[mi][nj][0], acc[mi][nj][1]));
                rmax[mi * 2 + 1] = fmaxf(rmax[mi * 2 + 1], fmaxf(acc[mi][nj][2], acc[mi][nj][3]));
            }
        CP_WAIT0();
        __syncthreads();
    }

    // reduce max: quad lanes, then across 4 wx via smem
#pragma unroll
    for (int i = 0; i < 4; i++) {
#pragma unroll
        for (int o = 1; o <= 2; o <<= 1)
            rmax[i] = fmaxf(rmax[i], __shfl_xor_sync(0xFFFFFFFFu, rmax[i], o));
    }
    if ((lane & 3) == 0) {
#pragma unroll
        for (int mi = 0; mi < 2; mi++)
#pragma unroll
            for (int h = 0; h < 2; h++) {
                int lr = wy * 32 + mi * 16 + (lane >> 2) + h * 8;
                RED[lr * 4 + wx] = rmax[mi * 2 + h];
            }
    }
    __syncthreads();

    if (tid < 128) {
        float sm = fmaxf(fmaxf(RED[tid * 4], RED[tid * 4 + 1]),
                         fmaxf(RED[tid * 4 + 2], RED[tid * 4 + 3]));
        float b2 = 14.426950408889634f / (1.001f - sm);   // beta * log2(e)
        BETA[tid] = b2;
        CV[tid] = b2 * sm;
    }
    __syncthreads();

    float lb[4], lc[4];
#pragma unroll
    for (int mi = 0; mi < 2; mi++)
#pragma unroll
        for (int h = 0; h < 2; h++) {
            int lr = wy * 32 + mi * 16 + (lane >> 2) + h * 8;
            lb[mi * 2 + h] = BETA[lr];
            lc[mi * 2 + h] = CV[lr];
        }

    // ---------------- PHASE 1: exp-sum ----------------
    load_tile(sb + YS_OFF, Yb, tid);
    CP_COMMIT();
    CP_WAIT0();
    __syncthreads();

    float rsum[4] = {0.f, 0.f, 0.f, 0.f};

    for (int mt = 0; mt < NT; mt++) {
        int cur = mt & 1;
        if (mt + 1 < NT) {
            load_tile(sb + YS_OFF + (cur ^ 1) * 32768, Yb + (size_t)(mt + 1) * 128 * CC, tid);
            CP_COMMIT();
        }
        uint32_t ybase = sb + YS_OFF + cur * 32768;

        float acc[2][4][4];
#pragma unroll
        for (int mi = 0; mi < 2; mi++)
#pragma unroll
            for (int nj = 0; nj < 4; nj++)
#pragma unroll
                for (int k = 0; k < 4; k++) acc[mi][nj][k] = 0.f;

#pragma unroll
        for (int kt = 0; kt < 8; kt++) {
            uint32_t a[2][4], bf[2][4];
#pragma unroll
            for (int mi = 0; mi < 2; mi++) {
                uint32_t addr = aB[mi] + ((uint32_t)((kt * 2 + hi) ^ aS[mi]) << 4);
                LDSM4(a[mi][0], a[mi][1], a[mi][2], a[mi][3], addr);
            }
#pragma unroll
            for (int g = 0; g < 2; g++) {
                uint32_t addr = ybase + bB[g] + ((uint32_t)((kt * 2 + hi) ^ bS[g]) << 4);
                LDSM4(bf[g][0], bf[g][1], bf[g][2], bf[g][3], addr);
            }
#pragma unroll
            for (int mi = 0; mi < 2; mi++)
#pragma unroll
                for (int g = 0; g < 2; g++) {
                    mma_bf16(acc[mi][2 * g],     a[mi], bf[g][0], bf[g][2]);
                    mma_bf16(acc[mi][2 * g + 1], a[mi], bf[g][1], bf[g][3]);
                }
        }
#pragma unroll
        for (int mi = 0; mi < 2; mi++)
#pragma unroll
            for (int nj = 0; nj < 4; nj++) {
                float b0 = lb[mi * 2], c0 = lc[mi * 2];
                float b1 = lb[mi * 2 + 1], c1 = lc[mi * 2 + 1];
                rsum[mi * 2]     += exp2f(fmaf(b0, acc[mi][nj][0], -c0))
                                  + exp2f(fmaf(b0, acc[mi][nj][1], -c0));
                rsum[mi * 2 + 1] += exp2f(fmaf(b1, acc[mi][nj][2], -c1))
                                  + exp2f(fmaf(b1, acc[mi][nj][3], -c1));
            }
        CP_WAIT0();
        __syncthreads();
    }

    // reduce sums: quad lanes, then 4 wx via smem
#pragma unroll
    for (int i = 0; i < 4; i++) {
#pragma unroll
        for (int o = 1; o <= 2; o <<= 1)
            rsum[i] += __shfl_xor_sync(0xFFFFFFFFu, rsum[i], o);
    }
    if ((lane & 3) == 0) {
#pragma unroll
        for (int mi = 0; mi < 2; mi++)
#pragma unroll
            for (int h = 0; h < 2; h++) {
                int lr = wy * 32 + mi * 16 + (lane >> 2) + h * 8;
                RED[lr * 4 + wx] = rsum[mi * 2 + h];
            }
    }
    __syncthreads();

    if (tid < 128) {
        float amax = 1.0f / (RED[tid * 4] + RED[tid * 4 + 1] + RED[tid * 4 + 2] + RED[tid * 4 + 3]);
#pragma unroll
        for (int o = 16; o > 0; o >>= 1) amax += __shfl_xor_sync(0xFFFFFFFFu, amax, o);
        if (lane == 0) RED[wid] = amax;
    }
    __syncthreads();
    if (tid == 0) {
        float s = RED[0] + RED[1] + RED[2] + RED[3];
        atomicAdd(&g_cx[b], s);
    }
}

// ------------------------------------------------------------------ finalize
__global__ void k_fin(float* __restrict__ out) {
    int b = threadIdx.x;
    if (b < BB) out[b] = -logf(g_cx[b] * (1.0f / NN));
}

// ------------------------------------------------------------------ launcher
extern "C" void kernel_launch(void* const* d_in, const int* in_sizes, int n_in,
                              void* d_out, int out_size) {
    const float* fx = (const float*)d_in[0];
    const float* fy = (const float*)d_in[1];
    float* out = (float*)d_out;

    cudaFuncSetAttribute(k_fused, cudaFuncAttributeMaxDynamicSharedMemorySize, SMEM_BYTES);

    k_init<<<1, 512>>>();
    k_mean<<<dim3(BB, 32), 128>>>(fy);
    k_norm<<<(BB * NN) / 8, 256>>>(fx, fy);
    k_fused<<<dim3(NT, BB), 512, SMEM_BYTES>>>();
    k_fin<<<1, 32>>>(out);
}